// round 13
// baseline (speedup 1.0000x reference)
#include <cuda_runtime.h>

#define N_FULL 50000
#define NLAT 10
#define MU 32
#define BATCH 8
#define TILE 4
#define MS 35               // m-stride per (pl,i) row  (35 ≡ 3 mod 32)
#define ENC_CHUNKS 50
#define ENC_VPC 250         // float4 per chunk (50*250 = 12500 = N/4)
#define ENC_BLOCKS (ENC_CHUNKS * BATCH)     // 400
#define WP_BLOCKS ((N_FULL + 255) / 256)    // 196 p-tiles

// Scratch (allocation-free rule: __device__ globals)
__device__ float  g_part[ENC_CHUNKS * BATCH * NLAT];  // [chunk][b*10+i] partial dots
__device__ float  g_encoded[BATCH * NLAT];
__device__ unsigned int g_ctr = 0;      // encode-blocks-done counter (reset each pass)
__device__ float4 g_dect[N_FULL * 4];   // [node][4 x float4]: 10 decoder vals + pad
__device__ float  g_w[NLAT * N_FULL * BATCH];  // cinv, layout [i][p][b] (16MB)

// ---------------------------------------------------------------------------
// Kernel 1: encode split-K partials; LAST block reduces g_part (+bias) into
// g_encoded and resets the counter (deterministic, graph-replay safe).
// ---------------------------------------------------------------------------
__global__ __launch_bounds__(256)
void encode_kernel(const float* __restrict__ x,
                   const float* __restrict__ ew,
                   const float* __restrict__ eb) {
    int bid = blockIdx.x;
    int tid = threadIdx.x;

    int b     = bid / ENC_CHUNKS;
    int chunk = bid % ENC_CHUNKS;
    int c0    = chunk * ENC_VPC;
    bool act  = tid < ENC_VPC;

    const float4* xv = (const float4*)(x + (size_t)b * N_FULL) + c0;
    float4 xa = act ? xv[tid] : make_float4(0.f, 0.f, 0.f, 0.f);

    float acc[NLAT];
    #pragma unroll
    for (int i = 0; i < NLAT; i++) {
        const float4* wv = (const float4*)(ew + (size_t)i * N_FULL) + c0;
        float4 wa = act ? wv[tid] : make_float4(0.f, 0.f, 0.f, 0.f);
        float s;
        s = xa.x * wa.x;
        s = fmaf(xa.y, wa.y, s);
        s = fmaf(xa.z, wa.z, s);
        s = fmaf(xa.w, wa.w, s);
        acc[i] = s;
    }

    __shared__ float red[8][NLAT];
    __shared__ bool  is_last;
    #pragma unroll
    for (int i = 0; i < NLAT; i++) {
        float s = acc[i];
        #pragma unroll
        for (int o = 16; o; o >>= 1) s += __shfl_down_sync(0xffffffffu, s, o);
        if ((tid & 31) == 0) red[tid >> 5][i] = s;
    }
    __syncthreads();
    if (tid < NLAT) {
        float s = 0.f;
        #pragma unroll
        for (int w = 0; w < 8; w++) s += red[w][tid];
        g_part[chunk * (BATCH * NLAT) + b * NLAT + tid] = s;
    }
    __threadfence();
    __syncthreads();
    if (tid == 0)
        is_last = (atomicAdd(&g_ctr, 1u) == ENC_BLOCKS - 1);
    __syncthreads();
    if (is_last) {
        __threadfence();
        if (tid < BATCH * NLAT) {
            float s = __ldg(&eb[tid - (tid / NLAT) * NLAT]);
            #pragma unroll
            for (int c = 0; c < ENC_CHUNKS; c++)
                s += g_part[c * (BATCH * NLAT) + tid];
            g_encoded[tid] = s;
        }
        __syncthreads();
        if (tid == 0) g_ctr = 0;   // reset for next graph replay
    }
}

// ---------------------------------------------------------------------------
// Kernel 2: wcompute + prep. grid (196, 11), 256 threads.
//   y<10 : one thread per (i=y, p); read bw coalesced along p; compute
//          cinv[b] = (1+e^-t)^2/1024 for 8 b's; store [i][p][b].
//   y==10: transpose decoder [10,N] -> g_dect [N][16] (runs concurrently)
// ---------------------------------------------------------------------------
__global__ __launch_bounds__(256)
void wprep_kernel(const float* __restrict__ bw,
                  const float* __restrict__ dec) {
    int tid = threadIdx.x;
    int i   = blockIdx.y;
    int p   = blockIdx.x * 256 + tid;

    if (i == NLAT) {
        // ---- prep: decoder transpose ----
        if (p >= N_FULL) return;
        float d[NLAT];
        #pragma unroll
        for (int k = 0; k < NLAT; k++) d[k] = dec[(size_t)k * N_FULL + p];
        g_dect[p * 4 + 0] = make_float4(d[0], d[1], d[2], d[3]);
        g_dect[p * 4 + 1] = make_float4(d[4], d[5], d[6], d[7]);
        g_dect[p * 4 + 2] = make_float4(d[8], d[9], 0.f, 0.f);
        return;
    }

    __shared__ float enc_s[BATCH * NLAT];
    if (tid < BATCH * NLAT) enc_s[tid] = g_encoded[tid];
    __syncthreads();
    if (p >= N_FULL) return;

    float t[BATCH];
    #pragma unroll
    for (int b = 0; b < BATCH; b++) t[b] = 0.f;
    #pragma unroll
    for (int k = 0; k < NLAT; k++) {
        float v = __ldg(&bw[(size_t)(i * NLAT + k) * N_FULL + p]);
        #pragma unroll
        for (int b = 0; b < BATCH; b++)
            t[b] = fmaf(enc_s[b * NLAT + k], v, t[b]);
    }
    float c[BATCH];
    #pragma unroll
    for (int b = 0; b < BATCH; b++) {
        float q = 1.f + __expf(-t[b]);                 // q = 1/w
        c[b] = fminf(q * q * (1.f / 1024.f), 1e12f);   // cinv = 1/(32w)^2
    }
    float4* dst = (float4*)&g_w[((size_t)i * N_FULL + p) * BATCH];
    dst[0] = make_float4(c[0], c[1], c[2], c[3]);
    dst[1] = make_float4(c[4], c[5], c[6], c[7]);
}

// ---------------------------------------------------------------------------
// Kernel 3: main. Per block: TILE=4 nodes, 128 threads, 16 blocks/SM.
//   E: read g_encoded (80 floats, pre-reduced)
//   A: stage neighbour indices via int4
//   B: cooperative gather — 3 lanes share one 64B decoder row (1 L1 line)
//   C: prefix sums over m (register-batched), 40 row-threads
//   D: 128 threads = 4 nodes x 8 b x 4 i-quarters; cinv from g_w (coalesced)
// ---------------------------------------------------------------------------
__global__ __launch_bounds__(128, 16)
void main_kernel(const int*  __restrict__ nb,
                 float*      __restrict__ out) {
    __shared__ float enc_s[BATCH * NLAT];
    __shared__ int   nbs[TILE * MU];          // 512B; reused as float[128] for D-reduce
    __shared__ float P0s[TILE * NLAT * MS];   // [pl][i][m], m-stride 35
    __shared__ float P2s[TILE * NLAT * MS];

    int tid = threadIdx.x;
    int p0  = blockIdx.x * TILE;

    // ---- Phase E: read reduced encode ----
    if (tid < BATCH * NLAT) enc_s[tid] = g_encoded[tid];

    // ---- Phase A: stage indices (128 ints = 32 int4) ----
    if (tid < TILE * MU / 4)
        ((int4*)nbs)[tid] = __ldg(&((const int4*)(nb + (size_t)p0 * MU))[tid]);
    __syncthreads();

    // ---- Phase B: cooperative gather (3 lanes per index -> 1 line) ----
    #pragma unroll
    for (int it = 0; it < TILE * MU * 3 / 128; it++) {   // 3 iters
        int t = it * 128 + tid;
        int s = t / 3;                 // index id (0..127)
        int chunk = t - s * 3;         // 0,1,2
        int j = nbs[s];
        float4 v = g_dect[j * 4 + chunk];
        int base = (s >> 5) * (NLAT * MS) + (s & 31) + chunk * (4 * MS);
        P0s[base]          = v.x;
        P0s[base + MS]     = v.y;
        if (chunk != 2) {
            P0s[base + 2 * MS] = v.z;
            P0s[base + 3 * MS] = v.w;
        }
    }
    __syncthreads();

    // ---- Phase C: prefix sums, register-batched in rounds of 4 (40 rows) ----
    if (tid < TILE * NLAT) {
        int base = tid * MS;
        float s0 = 0.f, s2 = 0.f;
        #pragma unroll
        for (int h = 0; h < 8; h++) {
            float g[4];
            #pragma unroll
            for (int q = 0; q < 4; q++) g[q] = P0s[base + h * 4 + q];  // batched
            #pragma unroll
            for (int q = 0; q < 4; q++) {
                int m = h * 4 + q;
                s0 += g[q];
                s2 = fmaf(g[q], (float)(m * m), s2);
                P0s[base + m] = s0;
                P2s[base + m] = s2;
            }
        }
    }
    __syncthreads();

    // ---- Phase D: 128 threads = 4 nodes x 8 b x 4 i-quarters ----
    float* redf = (float*)nbs;
    {
        int b  = tid & 7;
        int pl = (tid >> 3) & 3;
        int iq = tid >> 5;             // warp id: uniform per warp
        int p  = p0 + pl;

        float acc = 0.f;
        for (int i = iq; i < NLAT; i += 4) {
            // coalesced: warp covers 32 consecutive floats of g_w[i][p0..][b]
            float cinv = __ldg(&g_w[((size_t)i * N_FULL + p) * BATCH + b]);
            float u = rsqrtf(cinv);                       // u = 32w
            int K = min(MU, (int)u + 1);                  // #window terms
            float S2K = (float)((K - 1) * K * (2 * K - 1)) * (1.f / 6.f);
            int idx = (pl * NLAT + i) * MS + (K - 1);
            float P0 = P0s[idx];
            float P2 = P2s[idx];
            float norm = (float)K - cinv * S2K;
            float sm = __fdividef(P0 - cinv * P2, norm);
            acc = fmaf(enc_s[b * NLAT + i], sm, acc);
        }
        redf[tid] = acc;
    }
    __syncthreads();
    if (tid < 32) {
        int b  = tid & 7;
        int pl = tid >> 3;
        out[(size_t)b * N_FULL + p0 + pl] =
            redf[tid] + redf[tid + 32] + redf[tid + 64] + redf[tid + 96];
    }
}

// ---------------------------------------------------------------------------
extern "C" void kernel_launch(void* const* d_in, const int* in_sizes, int n_in,
                              void* d_out, int out_size) {
    const float* x   = (const float*)d_in[0];
    const float* ew  = (const float*)d_in[1];
    const float* ebv = (const float*)d_in[2];
    const float* dec = (const float*)d_in[3];
    const float* bw  = (const float*)d_in[4];
    const int*   nb  = (const int*)d_in[5];
    float* out = (float*)d_out;

    encode_kernel<<<ENC_BLOCKS, 256>>>(x, ew, ebv);
    wprep_kernel<<<dim3(WP_BLOCKS, NLAT + 1), 256>>>(bw, dec);
    main_kernel<<<N_FULL / TILE, 128>>>(nb, out);
}

// round 14
// speedup vs baseline: 1.0601x; 1.0601x over previous
#include <cuda_runtime.h>

#define N_FULL 50000
#define NLAT 10
#define MU 32
#define BATCH 8
#define TILE 8
#define MS 35               // m-stride per (pl,i) row  (35 ≡ 3 mod 32)
#define ENC_CHUNKS 50
#define ENC_VPC 250         // float4 per chunk (50*250 = 12500 = N/4)
#define ENC_TOTAL (ENC_CHUNKS * BATCH * 2)  // 800 encode blocks (i split in halves)
#define PREP_BLOCKS ((N_FULL + 255) / 256)  // 196

// Scratch (allocation-free rule: __device__ globals)
__device__ float  g_part[ENC_CHUNKS * BATCH * NLAT];  // [chunk][b*10+i] partial dots
__device__ float  g_encoded[BATCH * NLAT];
__device__ unsigned int g_ctr = 0;      // encode-blocks-done counter (reset each pass)
__device__ float4 g_dect[N_FULL * 4];   // [node][4 x float4]: 10 decoder vals + pad

// ---------------------------------------------------------------------------
// Kernel 1 (fused): blocks [0,800) encode split-K partials over (chunk, b,
// i-half); the LAST encode block reduces g_part (+bias) into g_encoded and
// resets the counter. Blocks [800,996) transpose decoder into g_dect.
// ---------------------------------------------------------------------------
__global__ __launch_bounds__(256)
void encprep_kernel(const float* __restrict__ x,
                    const float* __restrict__ ew,
                    const float* __restrict__ dec,
                    const float* __restrict__ eb) {
    int bid = blockIdx.x;
    int tid = threadIdx.x;

    if (bid < ENC_TOTAL) {
        int ihalf = bid / (ENC_CHUNKS * BATCH);
        int rem   = bid % (ENC_CHUNKS * BATCH);
        int b     = rem / ENC_CHUNKS;
        int chunk = rem % ENC_CHUNKS;
        int c0    = chunk * ENC_VPC;
        bool act  = tid < ENC_VPC;

        const float4* xv = (const float4*)(x + (size_t)b * N_FULL) + c0;
        float4 xa = act ? xv[tid] : make_float4(0.f, 0.f, 0.f, 0.f);

        float acc[5];
        #pragma unroll
        for (int ii = 0; ii < 5; ii++) {
            int i = ihalf * 5 + ii;
            const float4* wv = (const float4*)(ew + (size_t)i * N_FULL) + c0;
            float4 wa = act ? wv[tid] : make_float4(0.f, 0.f, 0.f, 0.f);
            float s;
            s = xa.x * wa.x;
            s = fmaf(xa.y, wa.y, s);
            s = fmaf(xa.z, wa.z, s);
            s = fmaf(xa.w, wa.w, s);
            acc[ii] = s;
        }

        __shared__ float red[8][5];
        __shared__ bool  is_last;
        #pragma unroll
        for (int ii = 0; ii < 5; ii++) {
            float s = acc[ii];
            #pragma unroll
            for (int o = 16; o; o >>= 1) s += __shfl_down_sync(0xffffffffu, s, o);
            if ((tid & 31) == 0) red[tid >> 5][ii] = s;
        }
        __syncthreads();
        if (tid < 5) {
            float s = 0.f;
            #pragma unroll
            for (int w = 0; w < 8; w++) s += red[w][tid];
            g_part[chunk * (BATCH * NLAT) + b * NLAT + ihalf * 5 + tid] = s;
        }
        __threadfence();
        __syncthreads();
        if (tid == 0)
            is_last = (atomicAdd(&g_ctr, 1u) == ENC_TOTAL - 1);
        __syncthreads();
        if (is_last) {
            __threadfence();   // acquire: see all blocks' g_part
            if (tid < BATCH * NLAT) {
                float s = __ldg(&eb[tid - (tid / NLAT) * NLAT]);
                #pragma unroll
                for (int c = 0; c < ENC_CHUNKS; c++)
                    s += g_part[c * (BATCH * NLAT) + tid];
                g_encoded[tid] = s;
            }
            __syncthreads();
            if (tid == 0) g_ctr = 0;   // reset for next graph replay
        }
    } else {
        int j = (bid - ENC_TOTAL) * 256 + tid;
        if (j >= N_FULL) return;
        float d[NLAT];
        #pragma unroll
        for (int i = 0; i < NLAT; i++) d[i] = dec[(size_t)i * N_FULL + j];
        g_dect[j * 4 + 0] = make_float4(d[0], d[1], d[2], d[3]);
        g_dect[j * 4 + 1] = make_float4(d[4], d[5], d[6], d[7]);
        g_dect[j * 4 + 2] = make_float4(d[8], d[9], 0.f, 0.f);
    }
}

// ---------------------------------------------------------------------------
// Kernel 2: main (fused bandwidth compute). Per block: TILE=8 nodes, 128 thr.
//   E: read g_encoded (80 floats, pre-reduced)
//   A: stage neighbour indices via int4
//   F: stage bw tile [100 ik-rows x 8 nodes] coalesced into smem (3.2KB)
//   B: cooperative gather — 3 lanes share one 64B decoder row (1 L1 line)
//   C: prefix sums over m (register-batched rounds of 8), 80 row-threads
//   D: per (node,b,i-half): dot+sigmoid from smem; closed-form window via K
// ---------------------------------------------------------------------------
__global__ __launch_bounds__(128)
void main_kernel(const float* __restrict__ bw,
                 const int*  __restrict__ nb,
                 float*      __restrict__ out) {
    __shared__ float enc_s[BATCH * NLAT];
    __shared__ int   nbs[TILE * MU];          // 1KB; reused as float[128] for D-reduce
    __shared__ float bws[NLAT * NLAT * TILE]; // 3.2KB: [i*10+k][pl]
    __shared__ float P0s[TILE * NLAT * MS];   // [pl][i][m], m-stride 35
    __shared__ float P2s[TILE * NLAT * MS];

    int tid = threadIdx.x;
    int p0  = blockIdx.x * TILE;

    // ---- Phase E: read reduced encode ----
    if (tid < BATCH * NLAT) enc_s[tid] = g_encoded[tid];

    // ---- Phase A: stage indices (256 ints = 64 int4) ----
    if (tid < TILE * MU / 4)
        ((int4*)nbs)[tid] = __ldg(&((const int4*)(nb + (size_t)p0 * MU))[tid]);

    // ---- Phase F: stage bw tile (100 rows x 8 nodes, 32B-coalesced) ----
    #pragma unroll
    for (int it = 0; it < 7; it++) {
        int t = it * 128 + tid;
        if (t < NLAT * NLAT * TILE) {
            int ik = t >> 3, pl = t & 7;
            bws[t] = __ldg(&bw[(size_t)ik * N_FULL + p0 + pl]);
        }
    }
    __syncthreads();

    // ---- Phase B: cooperative gather (3 lanes per index -> 1 line) ----
    #pragma unroll
    for (int it = 0; it < TILE * MU * 3 / 128; it++) {   // 6 iters
        int t = it * 128 + tid;
        int s = t / 3;                 // index id (0..255)
        int chunk = t - s * 3;         // 0,1,2
        int j = nbs[s];
        float4 v = g_dect[j * 4 + chunk];
        int base = (s >> 5) * (NLAT * MS) + (s & 31) + chunk * (4 * MS);
        P0s[base]          = v.x;
        P0s[base + MS]     = v.y;
        if (chunk != 2) {
            P0s[base + 2 * MS] = v.z;
            P0s[base + 3 * MS] = v.w;
        }
    }
    __syncthreads();

    // ---- Phase C: prefix sums, register-batched in rounds of 8 (80 rows) ----
    if (tid < TILE * NLAT) {
        int base = tid * MS;
        float s0 = 0.f, s2 = 0.f;
        #pragma unroll
        for (int h = 0; h < 4; h++) {
            float g[8];
            #pragma unroll
            for (int q = 0; q < 8; q++) g[q] = P0s[base + h * 8 + q];  // batched
            #pragma unroll
            for (int q = 0; q < 8; q++) {
                int m = h * 8 + q;
                s0 += g[q];
                s2 = fmaf(g[q], (float)(m * m), s2);
                P0s[base + m] = s0;
                P2s[base + m] = s2;
            }
        }
    }
    __syncthreads();

    // ---- Phase D: 128 threads = 8 nodes x 8 b x 2 i-halves (fused w) ----
    float* redf = (float*)nbs;
    {
        int b    = tid & 7;
        int pl   = (tid >> 3) & 7;
        int half = tid >> 6;

        float acc = 0.f;
        #pragma unroll
        for (int ii = 0; ii < 5; ii++) {
            int i = half * 5 + ii;
            float t = 0.f;
            #pragma unroll
            for (int k = 0; k < NLAT; k++)
                t = fmaf(enc_s[b * NLAT + k], bws[(i * NLAT + k) * TILE + pl], t);
            float q = 1.f + __expf(-t);                     // q = 1/w
            float cinv = fminf(q * q * (1.f / 1024.f), 1e12f);  // 1/(32w)^2
            float u = __fdividef(32.f, q);                  // 32w
            int K = min(MU, (int)u + 1);                    // #window terms
            float S2K = (float)((K - 1) * K * (2 * K - 1)) * (1.f / 6.f);
            int idx = (pl * NLAT + i) * MS + (K - 1);
            float P0 = P0s[idx];
            float P2 = P2s[idx];
            float norm = (float)K - cinv * S2K;
            float sm = __fdividef(P0 - cinv * P2, norm);
            acc = fmaf(enc_s[b * NLAT + i], sm, acc);
        }
        redf[tid] = acc;
    }
    __syncthreads();
    if (tid < 64) {
        int b  = tid & 7;
        int pl = tid >> 3;
        out[(size_t)b * N_FULL + p0 + pl] = redf[tid] + redf[tid + 64];
    }
}

// ---------------------------------------------------------------------------
extern "C" void kernel_launch(void* const* d_in, const int* in_sizes, int n_in,
                              void* d_out, int out_size) {
    const float* x   = (const float*)d_in[0];
    const float* ew  = (const float*)d_in[1];
    const float* ebv = (const float*)d_in[2];
    const float* dec = (const float*)d_in[3];
    const float* bw  = (const float*)d_in[4];
    const int*   nb  = (const int*)d_in[5];
    float* out = (float*)d_out;

    encprep_kernel<<<ENC_TOTAL + PREP_BLOCKS, 256>>>(x, ew, dec, ebv);
    main_kernel<<<N_FULL / TILE, 128>>>(bw, nb, out);
}